// round 2
// baseline (speedup 1.0000x reference)
#include <cuda_runtime.h>
#include <math.h>

// Problem dims
#define Bz 64
#define Sz 128
#define Hz 1024
#define Ez 512
#define Az 512
#define Vz 32000

// Output layout (floats): logits[B*V], new_hidden[2*B*H], new_cell[2*B*H], alpha[B*S]
#define OFF_LOGITS 0
#define OFF_H0     (Bz*Vz)                 // 2048000
#define OFF_H1     (OFF_H0 + Bz*Hz)        // +65536
#define OFF_C0     (OFF_H0 + 2*Bz*Hz)      // 2179072
#define OFF_C1     (OFF_C0 + Bz*Hz)
#define OFF_ALPHA  (OFF_C0 + 2*Bz*Hz)      // 2310144

// Scratch (device globals; no allocations allowed)
__device__ float g_dproj[Bz * Az];          // W_dec @ top   (64 x 512)
__device__ float g_scorep[8 * Bz * Sz];     // 8 column-block partial scores
__device__ float g_context[Bz * 2 * Hz];    // attention context (64 x 2048)
__device__ float g_gates[Bz * 4 * Hz];      // LSTM gate pre-activations

// ---------------------------------------------------------------------------
// Generic 64x64 tile fp32 GEMM: C[M,N] = A[M,K] @ B[N,K]^T  (+ epilogue)
// 256 threads, 4x4 microtile, BK=16.
// ---------------------------------------------------------------------------
template <class Cfg>
__global__ __launch_bounds__(256) void sgemm64(Cfg cfg) {
    __shared__ float As[16][68];   // [k][m]
    __shared__ float Bs[16][68];   // [k][n]
    const int bm = blockIdx.y * 64;
    const int bn = blockIdx.x * 64;
    const int tid = threadIdx.x;
    const int tx = tid & 15, ty = tid >> 4;
    const int kk = tid & 15, r0 = tid >> 4;

    float acc[4][4] = {};
    for (int k0 = 0; k0 < cfg.K; k0 += 16) {
#pragma unroll
        for (int i = 0; i < 4; i++)
            As[kk][r0 + i * 16] = cfg.loadA(bm + r0 + i * 16, k0 + kk);
#pragma unroll
        for (int i = 0; i < 4; i++)
            Bs[kk][r0 + i * 16] = cfg.loadB(bn + r0 + i * 16, k0 + kk);
        __syncthreads();
#pragma unroll
        for (int k = 0; k < 16; k++) {
            float4 a4 = *(const float4*)&As[k][ty * 4];
            float4 b4 = *(const float4*)&Bs[k][tx * 4];
            float av[4] = {a4.x, a4.y, a4.z, a4.w};
            float bv[4] = {b4.x, b4.y, b4.z, b4.w};
#pragma unroll
            for (int i = 0; i < 4; i++)
#pragma unroll
                for (int j = 0; j < 4; j++) acc[i][j] += av[i] * bv[j];
        }
        __syncthreads();
    }
    cfg.store(bm, bn, ty, tx, acc);
}

// ---- Config: dproj = hidden[1] @ W_dec^T  (64 x 512, K=1024) --------------
struct DprojCfg {
    int K;
    const float* __restrict__ hid;   // hidden base (L,B,H)
    const float* __restrict__ Wdec;  // (A,H)
    __device__ __forceinline__ float loadA(int m, int k) const {
        return hid[(Bz + m) * Hz + k];            // hidden[-1] = layer 1
    }
    __device__ __forceinline__ float loadB(int n, int k) const {
        return Wdec[n * Hz + k];
    }
    __device__ __forceinline__ void store(int bm, int bn, int ty, int tx,
                                          const float (&acc)[4][4]) const {
#pragma unroll
        for (int i = 0; i < 4; i++)
#pragma unroll
            for (int j = 0; j < 4; j++)
                g_dproj[(bm + ty * 4 + i) * Az + bn + tx * 4 + j] = acc[i][j];
    }
};

// ---- Config: LSTM0 gates (64 x 4096, K = 512+2048+1024 = 3584) ------------
struct Lstm0Cfg {
    int K;
    const int* __restrict__ token;
    const float* __restrict__ emb;    // (V,E)
    const float* __restrict__ hid;    // hidden base; layer 0
    const float* __restrict__ Wih;    // (4H, E+2H)
    const float* __restrict__ Whh;    // (4H, H)
    const float* __restrict__ bih;
    const float* __restrict__ bhh;
    __device__ __forceinline__ float loadA(int m, int k) const {
        if (k < Ez) return emb[token[m] * Ez + k];
        if (k < Ez + 2 * Hz) return g_context[m * 2 * Hz + (k - Ez)];
        return hid[m * Hz + (k - Ez - 2 * Hz)];
    }
    __device__ __forceinline__ float loadB(int n, int k) const {
        if (k < Ez + 2 * Hz) return Wih[n * (Ez + 2 * Hz) + k];
        return Whh[n * Hz + (k - Ez - 2 * Hz)];
    }
    __device__ __forceinline__ void store(int bm, int bn, int ty, int tx,
                                          const float (&acc)[4][4]) const {
#pragma unroll
        for (int i = 0; i < 4; i++)
#pragma unroll
            for (int j = 0; j < 4; j++) {
                int n = bn + tx * 4 + j;
                g_gates[(bm + ty * 4 + i) * 4 * Hz + n] = acc[i][j] + bih[n] + bhh[n];
            }
    }
};

// ---- Config: LSTM1 gates (64 x 4096, K = 1024+1024) -----------------------
struct Lstm1Cfg {
    int K;
    const float* __restrict__ h0new;  // d_out new_hidden[0]
    const float* __restrict__ hid;    // hidden base; layer 1
    const float* __restrict__ Wih;    // (4H, H)
    const float* __restrict__ Whh;    // (4H, H)
    const float* __restrict__ bih;
    const float* __restrict__ bhh;
    __device__ __forceinline__ float loadA(int m, int k) const {
        if (k < Hz) return h0new[m * Hz + k];
        return hid[(Bz + m) * Hz + (k - Hz)];
    }
    __device__ __forceinline__ float loadB(int n, int k) const {
        if (k < Hz) return Wih[n * Hz + k];
        return Whh[n * Hz + (k - Hz)];
    }
    __device__ __forceinline__ void store(int bm, int bn, int ty, int tx,
                                          const float (&acc)[4][4]) const {
#pragma unroll
        for (int i = 0; i < 4; i++)
#pragma unroll
            for (int j = 0; j < 4; j++) {
                int n = bn + tx * 4 + j;
                g_gates[(bm + ty * 4 + i) * 4 * Hz + n] = acc[i][j] + bih[n] + bhh[n];
            }
    }
};

// ---- Config: fc logits (64 x 32000, K = 1024+2048 = 3072) -----------------
struct FcCfg {
    int K;
    const float* __restrict__ h1new;  // d_out new_hidden[1]
    const float* __restrict__ fcW;    // (V, 3H)
    const float* __restrict__ fcb;
    float* __restrict__ logits;       // d_out
    __device__ __forceinline__ float loadA(int m, int k) const {
        if (k < Hz) return h1new[m * Hz + k];
        return g_context[m * 2 * Hz + (k - Hz)];
    }
    __device__ __forceinline__ float loadB(int n, int k) const {
        return fcW[n * 3 * Hz + k];
    }
    __device__ __forceinline__ void store(int bm, int bn, int ty, int tx,
                                          const float (&acc)[4][4]) const {
#pragma unroll
        for (int i = 0; i < 4; i++)
#pragma unroll
            for (int j = 0; j < 4; j++) {
                int n = bn + tx * 4 + j;
                logits[(bm + ty * 4 + i) * Vz + n] = acc[i][j] + fcb[n];
            }
    }
};

// ---------------------------------------------------------------------------
// Attention score kernel: rows m = s*B + b over enc_out (contiguous!),
// cols n = attention dim a.  score partial per column-block:
//   scorep[blk][m] = sum_{a in blk} v[a] * tanh(encproj[m,a] + dproj[b,a])
// grid = (8, 128), same 64x64 tiling.
// ---------------------------------------------------------------------------
__global__ __launch_bounds__(256) void attn_score_kernel(
    const float* __restrict__ enc,   // (S*B, 2H) row-major
    const float* __restrict__ Wenc,  // (A, 2H)
    const float* __restrict__ vw) {
    __shared__ float As[16][68];
    __shared__ float Bs[16][68];
    __shared__ float red[64][17];
    const int bm = blockIdx.y * 64;
    const int bn = blockIdx.x * 64;
    const int tid = threadIdx.x;
    const int tx = tid & 15, ty = tid >> 4;
    const int kk = tid & 15, r0 = tid >> 4;
    const int K = 2 * Hz;

    float acc[4][4] = {};
    for (int k0 = 0; k0 < K; k0 += 16) {
#pragma unroll
        for (int i = 0; i < 4; i++)
            As[kk][r0 + i * 16] = enc[(bm + r0 + i * 16) * K + k0 + kk];
#pragma unroll
        for (int i = 0; i < 4; i++)
            Bs[kk][r0 + i * 16] = Wenc[(bn + r0 + i * 16) * K + k0 + kk];
        __syncthreads();
#pragma unroll
        for (int k = 0; k < 16; k++) {
            float4 a4 = *(const float4*)&As[k][ty * 4];
            float4 b4 = *(const float4*)&Bs[k][tx * 4];
            float av[4] = {a4.x, a4.y, a4.z, a4.w};
            float bv[4] = {b4.x, b4.y, b4.z, b4.w};
#pragma unroll
            for (int i = 0; i < 4; i++)
#pragma unroll
                for (int j = 0; j < 4; j++) acc[i][j] += av[i] * bv[j];
        }
        __syncthreads();
    }

    // epilogue: tanh + dot with v, reduce across the 64-col tile per row
    float vv[4];
#pragma unroll
    for (int j = 0; j < 4; j++) vv[j] = vw[bn + tx * 4 + j];
#pragma unroll
    for (int i = 0; i < 4; i++) {
        int m = bm + ty * 4 + i;
        int b = m & (Bz - 1);
        float rs = 0.f;
#pragma unroll
        for (int j = 0; j < 4; j++) {
            int n = bn + tx * 4 + j;
            rs += vv[j] * tanhf(acc[i][j] + g_dproj[b * Az + n]);
        }
        red[ty * 4 + i][tx] = rs;
    }
    __syncthreads();
    if (tid < 64) {
        float s = 0.f;
#pragma unroll
        for (int t = 0; t < 16; t++) s += red[tid][t];
        g_scorep[blockIdx.x * (Bz * Sz) + bm + tid] = s;
    }
}

// ---------------------------------------------------------------------------
// Softmax over S per batch row + context = alpha @ enc_t. One block per b.
// ---------------------------------------------------------------------------
__global__ __launch_bounds__(256) void softmax_context_kernel(
    const float* __restrict__ enc, float* __restrict__ alpha_out) {
    const int b = blockIdx.x;
    const int tid = threadIdx.x;
    __shared__ float sa[Sz];
    __shared__ float tmp[Sz];

    if (tid < Sz) {
        float sc = 0.f;
#pragma unroll
        for (int p = 0; p < 8; p++) sc += g_scorep[p * (Bz * Sz) + tid * Bz + b];
        sa[tid] = sc;
        tmp[tid] = sc;
    }
    __syncthreads();
    for (int s = Sz / 2; s > 0; s >>= 1) {
        if (tid < s) tmp[tid] = fmaxf(tmp[tid], tmp[tid + s]);
        __syncthreads();
    }
    const float mx = tmp[0];
    __syncthreads();
    if (tid < Sz) {
        float e = expf(sa[tid] - mx);
        sa[tid] = e;
        tmp[tid] = e;
    }
    __syncthreads();
    for (int s = Sz / 2; s > 0; s >>= 1) {
        if (tid < s) tmp[tid] += tmp[tid + s];
        __syncthreads();
    }
    const float inv = 1.f / tmp[0];
    __syncthreads();
    if (tid < Sz) {
        float al = sa[tid] * inv;
        sa[tid] = al;
        alpha_out[b * Sz + tid] = al;
    }
    __syncthreads();

    // context[b, d] = sum_s alpha[s] * enc[(s*B + b)*2H + d]
    for (int d = tid; d < 2 * Hz; d += 256) {
        float s = 0.f;
#pragma unroll 8
        for (int t = 0; t < Sz; t++)
            s += sa[t] * enc[(t * Bz + b) * 2 * Hz + d];
        g_context[b * 2 * Hz + d] = s;
    }
}

// ---------------------------------------------------------------------------
// LSTM cell elementwise: gate order i, f, g, o
// ---------------------------------------------------------------------------
__global__ __launch_bounds__(256) void lstm_cell_kernel(
    const float* __restrict__ c_old, float* __restrict__ h_out,
    float* __restrict__ c_out) {
    const int idx = blockIdx.x * 256 + threadIdx.x;  // 0 .. B*H-1
    const int b = idx >> 10, j = idx & (Hz - 1);
    const float* __restrict__ g = g_gates + b * 4 * Hz;
    float gi = g[j], gf = g[Hz + j], gg = g[2 * Hz + j], go = g[3 * Hz + j];
    float si = 1.f / (1.f + expf(-gi));
    float sf = 1.f / (1.f + expf(-gf));
    float so = 1.f / (1.f + expf(-go));
    float cn = sf * c_old[idx] + si * tanhf(gg);
    float hn = so * tanhf(cn);
    c_out[idx] = cn;
    h_out[idx] = hn;
}

// ---------------------------------------------------------------------------
extern "C" void kernel_launch(void* const* d_in, const int* in_sizes, int n_in,
                              void* d_out, int out_size) {
    const int*   token  = (const int*)d_in[0];
    const float* hidden = (const float*)d_in[1];
    const float* cell   = (const float*)d_in[2];
    const float* enc    = (const float*)d_in[3];
    const float* emb    = (const float*)d_in[4];
    const float* Wenc   = (const float*)d_in[5];
    const float* Wdec   = (const float*)d_in[6];
    const float* vw     = (const float*)d_in[7];
    const float* Wih0   = (const float*)d_in[8];
    const float* Whh0   = (const float*)d_in[9];
    const float* bih0   = (const float*)d_in[10];
    const float* bhh0   = (const float*)d_in[11];
    const float* Wih1   = (const float*)d_in[12];
    const float* Whh1   = (const float*)d_in[13];
    const float* bih1   = (const float*)d_in[14];
    const float* bhh1   = (const float*)d_in[15];
    const float* fcW    = (const float*)d_in[16];
    const float* fcb    = (const float*)d_in[17];

    float* out    = (float*)d_out;
    float* logits = out + OFF_LOGITS;
    float* h0o    = out + OFF_H0;
    float* h1o    = out + OFF_H1;
    float* c0o    = out + OFF_C0;
    float* c1o    = out + OFF_C1;
    float* alpha  = out + OFF_ALPHA;

    // 1) dproj = hidden[1] @ W_dec^T
    {
        DprojCfg cfg{Hz, hidden, Wdec};
        sgemm64<<<dim3(Az / 64, 1), 256>>>(cfg);
    }
    // 2) attention scores (8 column-block partials, no atomics)
    attn_score_kernel<<<dim3(8, (Sz * Bz) / 64), 256>>>(enc, Wenc, vw);
    // 3) softmax + context
    softmax_context_kernel<<<Bz, 256>>>(enc, alpha);
    // 4) LSTM layer 0
    {
        Lstm0Cfg cfg{Ez + 2 * Hz + Hz, token, emb, hidden, Wih0, Whh0, bih0, bhh0};
        sgemm64<<<dim3(4 * Hz / 64, 1), 256>>>(cfg);
    }
    lstm_cell_kernel<<<(Bz * Hz) / 256, 256>>>(cell, h0o, c0o);
    // 5) LSTM layer 1
    {
        Lstm1Cfg cfg{2 * Hz, h0o, hidden, Wih1, Whh1, bih1, bhh1};
        sgemm64<<<dim3(4 * Hz / 64, 1), 256>>>(cfg);
    }
    lstm_cell_kernel<<<(Bz * Hz) / 256, 256>>>(cell + Bz * Hz, h1o, c1o);
    // 6) fc logits
    {
        FcCfg cfg{3 * Hz, h1o, fcW, fcb, logits};
        sgemm64<<<dim3(Vz / 64, 1), 256>>>(cfg);
    }
    (void)in_sizes; (void)n_in; (void)out_size;
}

// round 4
// speedup vs baseline: 2.2907x; 2.2907x over previous
#include <cuda_runtime.h>
#include <cuda_bf16.h>
#include <stdint.h>
#include <math.h>

// Problem dims
#define Bz 64
#define Sz 128
#define Hz 1024
#define Ez 512
#define Az 512
#define Vz 32000

// Output layout (floats): logits[B*V], new_hidden[2*B*H], new_cell[2*B*H], alpha[B*S]
#define OFF_LOGITS 0
#define OFF_H0     (Bz*Vz)
#define OFF_H1     (OFF_H0 + Bz*Hz)
#define OFF_C0     (OFF_H0 + 2*Bz*Hz)
#define OFF_C1     (OFF_C0 + Bz*Hz)
#define OFF_ALPHA  (OFF_C0 + 2*Bz*Hz)

// Scratch (device globals; no allocations allowed)
__device__ float g_dproj[Bz * Az];          // top @ W_dec^T   (64 x 512)
__device__ float g_scorep[8 * Bz * Sz];     // 8 column-block partial scores
__device__ float g_context[Bz * 2 * Hz];    // attention context (64 x 2048)
__device__ float g_gates[Bz * 4 * Hz];      // LSTM gate pre-activations

#define LDSTRIDE 40   // b16 elems per smem row: 32 data + 8 pad (conflict-free ldmatrix)

// ---------------------------------------------------------------------------
// MMA helpers
// ---------------------------------------------------------------------------
__device__ __forceinline__ uint32_t smem_u32(const void* p) {
    return (uint32_t)__cvta_generic_to_shared(p);
}

__device__ __forceinline__ void ldm_x4(uint32_t addr, uint32_t& r0, uint32_t& r1,
                                       uint32_t& r2, uint32_t& r3) {
    asm volatile("ldmatrix.sync.aligned.m8n8.x4.shared.b16 {%0,%1,%2,%3}, [%4];"
                 : "=r"(r0), "=r"(r1), "=r"(r2), "=r"(r3) : "r"(addr));
}

__device__ __forceinline__ void mma_bf16(float* c, const uint32_t a[4],
                                         uint32_t b0, uint32_t b1) {
    asm volatile(
        "mma.sync.aligned.m16n8k16.row.col.f32.bf16.bf16.f32 "
        "{%0,%1,%2,%3}, {%4,%5,%6,%7}, {%8,%9}, {%0,%1,%2,%3};"
        : "+f"(c[0]), "+f"(c[1]), "+f"(c[2]), "+f"(c[3])
        : "r"(a[0]), "r"(a[1]), "r"(a[2]), "r"(a[3]), "r"(b0), "r"(b1));
}

// Split one float4 into bf16 hi/lo and store 4 elements to each smem array.
__device__ __forceinline__ void split4(__nv_bfloat16* hi, __nv_bfloat16* lo,
                                       int idx, float4 v) {
    __nv_bfloat16 h0 = __float2bfloat16(v.x);
    __nv_bfloat16 h1 = __float2bfloat16(v.y);
    __nv_bfloat16 h2 = __float2bfloat16(v.z);
    __nv_bfloat16 h3 = __float2bfloat16(v.w);
    __nv_bfloat16 l0 = __float2bfloat16(v.x - __bfloat162float(h0));
    __nv_bfloat16 l1 = __float2bfloat16(v.y - __bfloat162float(h1));
    __nv_bfloat16 l2 = __float2bfloat16(v.z - __bfloat162float(h2));
    __nv_bfloat16 l3 = __float2bfloat16(v.w - __bfloat162float(h3));
    __nv_bfloat162* H = (__nv_bfloat162*)(hi + idx);
    __nv_bfloat162* L = (__nv_bfloat162*)(lo + idx);
    __nv_bfloat162 t;
    t.x = h0; t.y = h1; H[0] = t;
    t.x = h2; t.y = h3; H[1] = t;
    t.x = l0; t.y = l1; L[0] = t;
    t.x = l2; t.y = l3; L[1] = t;
}

__device__ __forceinline__ float4 ld4(const float* p) {
    return *(const float4*)p;
}

// ---------------------------------------------------------------------------
// Shared mainloop: C[64,64] tile of A[M,K] @ B[N,K]^T via bf16 hi/lo 3-pass mma.
// acc[j][*] : n-tile j (n8), regs (m,n),(m,n+1),(m+8,n),(m+8,n+1)
// ---------------------------------------------------------------------------
template <class Cfg>
__device__ __forceinline__ void run_mainloop(const Cfg& cfg, int bm, int bn,
                                             __nv_bfloat16* Ah, __nv_bfloat16* Al,
                                             __nv_bfloat16* Bh, __nv_bfloat16* Bl,
                                             float acc[4][4]) {
    const int tid  = threadIdx.x;
    const int row  = tid >> 2;            // 0..63  (tile row for loads)
    const int c4   = (tid & 3) << 2;      // 0,4,8,12 (float col within BK)
    const int lane = tid & 31;
    const int wid  = tid >> 5;
    const int wm   = (wid & 3) << 4;      // warp M offset (0..48)
    const int wn   = (wid >> 2) << 5;     // warp N offset (0 or 32)

    // ldmatrix per-thread offsets (in b16 elements)
    const int g = lane >> 3, r = lane & 7;
    // A tiles order: (m-lo,k-lo),(m-hi,k-lo),(m-lo,k-hi),(m-hi,k-hi)
    const int a_off = (wm + r + ((g & 1) << 3)) * LDSTRIDE + ((g >> 1) << 3);
    // B tiles order for n-pair: (n,k-lo),(n,k-hi),(n+8,k-lo),(n+8,k-hi)
    const int b_row = r + ((g >> 1) << 3);
    const int b_col = (g & 1) << 3;
    const int b_off0 = (wn + b_row) * LDSTRIDE + b_col;
    const int b_off1 = (wn + 16 + b_row) * LDSTRIDE + b_col;

    const uint32_t sAh = smem_u32(Ah), sAl = smem_u32(Al);
    const uint32_t sBh = smem_u32(Bh), sBl = smem_u32(Bl);

    float4 ra0, ra1, rb0, rb1;
    {
        const float* pa = cfg.rowA(bm + row, 0);
        const float* pb = cfg.rowB(bn + row, 0);
        ra0 = ld4(pa + c4);  ra1 = ld4(pa + c4 + 16);
        rb0 = ld4(pb + c4);  rb1 = ld4(pb + c4 + 16);
    }

    const int sidx = row * LDSTRIDE + c4;
    for (int k0 = 0;; k0 += 32) {
        split4(Ah, Al, sidx,      ra0);
        split4(Ah, Al, sidx + 16, ra1);
        split4(Bh, Bl, sidx,      rb0);
        split4(Bh, Bl, sidx + 16, rb1);
        __syncthreads();
        const bool more = (k0 + 32 < cfg.K);
        if (more) {  // prefetch next tile into registers (hidden under mma)
            const float* pa = cfg.rowA(bm + row, k0 + 32);
            const float* pb = cfg.rowB(bn + row, k0 + 32);
            ra0 = ld4(pa + c4);  ra1 = ld4(pa + c4 + 16);
            rb0 = ld4(pb + c4);  rb1 = ld4(pb + c4 + 16);
        }
#pragma unroll
        for (int ks = 0; ks < 2; ks++) {
            const int ko = ks << 4;  // 0 or 16 (b16 cols)
            uint32_t ah[4], al_[4];
            ldm_x4(sAh + 2 * (a_off + ko), ah[0], ah[1], ah[2], ah[3]);
            ldm_x4(sAl + 2 * (a_off + ko), al_[0], al_[1], al_[2], al_[3]);
#pragma unroll
            for (int p = 0; p < 2; p++) {
                const int bo = (p ? b_off1 : b_off0) + ko;
                uint32_t bh[4], bl_[4];
                ldm_x4(sBh + 2 * bo, bh[0], bh[1], bh[2], bh[3]);
                ldm_x4(sBl + 2 * bo, bl_[0], bl_[1], bl_[2], bl_[3]);
                float* c0 = acc[2 * p];
                float* c1 = acc[2 * p + 1];
                mma_bf16(c0, ah,  bh[0], bh[1]);   // hi*hi
                mma_bf16(c0, ah,  bl_[0], bl_[1]); // hi*lo
                mma_bf16(c0, al_, bh[0], bh[1]);   // lo*hi
                mma_bf16(c1, ah,  bh[2], bh[3]);
                mma_bf16(c1, ah,  bl_[2], bl_[3]);
                mma_bf16(c1, al_, bh[2], bh[3]);
            }
        }
        __syncthreads();
        if (!more) break;
    }
}

// ---------------------------------------------------------------------------
// Generic GEMM kernel with scalar-pair epilogue
// ---------------------------------------------------------------------------
template <class Cfg>
__global__ __launch_bounds__(256) void mma_gemm(Cfg cfg) {
    __shared__ __nv_bfloat16 Ah[64 * LDSTRIDE], Al[64 * LDSTRIDE];
    __shared__ __nv_bfloat16 Bh[64 * LDSTRIDE], Bl[64 * LDSTRIDE];
    float acc[4][4] = {};
    const int bm = blockIdx.y << 6, bn = blockIdx.x << 6;
    run_mainloop(cfg, bm, bn, Ah, Al, Bh, Bl, acc);

    const int lane = threadIdx.x & 31, wid = threadIdx.x >> 5;
    const int m0 = bm + ((wid & 3) << 4) + (lane >> 2);
    const int nb = bn + ((wid >> 2) << 5) + ((lane & 3) << 1);
#pragma unroll
    for (int j = 0; j < 4; j++) {
        const int n = nb + j * 8;
        cfg.store2(m0,     n, acc[j][0], acc[j][1]);
        cfg.store2(m0 + 8, n, acc[j][2], acc[j][3]);
    }
}

// ---- Configs ---------------------------------------------------------------
struct DprojCfg {
    int K;
    const float* hid;    // (L,B,H)
    const float* Wdec;   // (A,H)
    __device__ __forceinline__ const float* rowA(int m, int k0) const {
        return hid + (Bz + m) * Hz + k0;   // hidden[-1]
    }
    __device__ __forceinline__ const float* rowB(int n, int k0) const {
        return Wdec + n * Hz + k0;
    }
    __device__ __forceinline__ void store2(int m, int n, float v0, float v1) const {
        float2 t; t.x = v0; t.y = v1;
        *(float2*)&g_dproj[m * Az + n] = t;
    }
};

struct Lstm0Cfg {
    int K;  // 3584
    const int* token;
    const float* emb;    // (V,E)
    const float* hid;    // layer 0 hidden
    const float* Wih;    // (4H, E+2H)
    const float* Whh;    // (4H, H)
    const float* bih;
    const float* bhh;
    __device__ __forceinline__ const float* rowA(int m, int k0) const {
        if (k0 < Ez)          return emb + token[m] * Ez + k0;
        if (k0 < Ez + 2 * Hz) return g_context + m * 2 * Hz + (k0 - Ez);
        return hid + m * Hz + (k0 - Ez - 2 * Hz);
    }
    __device__ __forceinline__ const float* rowB(int n, int k0) const {
        if (k0 < Ez + 2 * Hz) return Wih + n * (Ez + 2 * Hz) + k0;
        return Whh + n * Hz + (k0 - Ez - 2 * Hz);
    }
    __device__ __forceinline__ void store2(int m, int n, float v0, float v1) const {
        float2 t;
        t.x = v0 + bih[n] + bhh[n];
        t.y = v1 + bih[n + 1] + bhh[n + 1];
        *(float2*)&g_gates[m * 4 * Hz + n] = t;
    }
};

struct Lstm1Cfg {
    int K;  // 2048
    const float* h0new;
    const float* hid;    // layer 1 hidden
    const float* Wih;    // (4H, H)
    const float* Whh;    // (4H, H)
    const float* bih;
    const float* bhh;
    __device__ __forceinline__ const float* rowA(int m, int k0) const {
        if (k0 < Hz) return h0new + m * Hz + k0;
        return hid + (Bz + m) * Hz + (k0 - Hz);
    }
    __device__ __forceinline__ const float* rowB(int n, int k0) const {
        if (k0 < Hz) return Wih + n * Hz + k0;
        return Whh + n * Hz + (k0 - Hz);
    }
    __device__ __forceinline__ void store2(int m, int n, float v0, float v1) const {
        float2 t;
        t.x = v0 + bih[n] + bhh[n];
        t.y = v1 + bih[n + 1] + bhh[n + 1];
        *(float2*)&g_gates[m * 4 * Hz + n] = t;
    }
};

struct FcCfg {
    int K;  // 3072
    const float* h1new;
    const float* fcW;    // (V, 3H)
    const float* fcb;
    float* logits;
    __device__ __forceinline__ const float* rowA(int m, int k0) const {
        if (k0 < Hz) return h1new + m * Hz + k0;
        return g_context + m * 2 * Hz + (k0 - Hz);
    }
    __device__ __forceinline__ const float* rowB(int n, int k0) const {
        return fcW + n * 3 * Hz + k0;
    }
    __device__ __forceinline__ void store2(int m, int n, float v0, float v1) const {
        float2 t;
        t.x = v0 + fcb[n];
        t.y = v1 + fcb[n + 1];
        *(float2*)&logits[m * Vz + n] = t;
    }
};

// ---------------------------------------------------------------------------
// Attention: energy GEMM + tanh + v-dot + per-row reduce into column partials
// rows m = s*B + b (enc rows contiguous), cols n = attention dim
// ---------------------------------------------------------------------------
struct AttnCfg {
    int K;  // 2048
    const float* enc;    // (S*B, 2H)
    const float* Wenc;   // (A, 2H)
    const float* vw;     // (A,)
    __device__ __forceinline__ const float* rowA(int m, int k0) const {
        return enc + m * 2 * Hz + k0;
    }
    __device__ __forceinline__ const float* rowB(int n, int k0) const {
        return Wenc + n * 2 * Hz + k0;
    }
    __device__ __forceinline__ void store2(int, int, float, float) const {}
};

__global__ __launch_bounds__(256) void attn_mma_kernel(AttnCfg cfg) {
    __shared__ __nv_bfloat16 Ah[64 * LDSTRIDE], Al[64 * LDSTRIDE];
    __shared__ __nv_bfloat16 Bh[64 * LDSTRIDE], Bl[64 * LDSTRIDE];
    __shared__ float red[64][2];
    float acc[4][4] = {};
    const int bm = blockIdx.y << 6, bn = blockIdx.x << 6;
    run_mainloop(cfg, bm, bn, Ah, Al, Bh, Bl, acc);

    const int lane = threadIdx.x & 31, wid = threadIdx.x >> 5;
    const int wnI = wid >> 2;                       // 0/1
    const int ml  = ((wid & 3) << 4) + (lane >> 2); // local row (lower of pair)
    const int b0  = (bm + ml) & (Bz - 1);
    const int b1  = (bm + ml + 8) & (Bz - 1);
    const int nb  = bn + (wnI << 5) + ((lane & 3) << 1);

    float rs0 = 0.f, rs1 = 0.f;
#pragma unroll
    for (int j = 0; j < 4; j++) {
        const int n = nb + j * 8;
        const float v0 = cfg.vw[n], v1 = cfg.vw[n + 1];
        rs0 += v0 * tanhf(acc[j][0] + g_dproj[b0 * Az + n]);
        rs0 += v1 * tanhf(acc[j][1] + g_dproj[b0 * Az + n + 1]);
        rs1 += v0 * tanhf(acc[j][2] + g_dproj[b1 * Az + n]);
        rs1 += v1 * tanhf(acc[j][3] + g_dproj[b1 * Az + n + 1]);
    }
    // reduce over the 4 lanes of each row-quad
    rs0 += __shfl_xor_sync(0xffffffffu, rs0, 1);
    rs0 += __shfl_xor_sync(0xffffffffu, rs0, 2);
    rs1 += __shfl_xor_sync(0xffffffffu, rs1, 1);
    rs1 += __shfl_xor_sync(0xffffffffu, rs1, 2);
    if ((lane & 3) == 0) {
        red[ml][wnI]     = rs0;
        red[ml + 8][wnI] = rs1;
    }
    __syncthreads();
    if (threadIdx.x < 64)
        g_scorep[blockIdx.x * (Bz * Sz) + bm + threadIdx.x] =
            red[threadIdx.x][0] + red[threadIdx.x][1];
}

// ---------------------------------------------------------------------------
// Softmax over S per batch row + context = alpha @ enc_t. One block per b.
// ---------------------------------------------------------------------------
__global__ __launch_bounds__(256) void softmax_context_kernel(
    const float* __restrict__ enc, float* __restrict__ alpha_out) {
    const int b = blockIdx.x;
    const int tid = threadIdx.x;
    __shared__ float sa[Sz];
    __shared__ float tmp[Sz];

    if (tid < Sz) {
        float sc = 0.f;
#pragma unroll
        for (int p = 0; p < 8; p++) sc += g_scorep[p * (Bz * Sz) + tid * Bz + b];
        sa[tid] = sc;
        tmp[tid] = sc;
    }
    __syncthreads();
    for (int s = Sz / 2; s > 0; s >>= 1) {
        if (tid < s) tmp[tid] = fmaxf(tmp[tid], tmp[tid + s]);
        __syncthreads();
    }
    const float mx = tmp[0];
    __syncthreads();
    if (tid < Sz) {
        float e = expf(sa[tid] - mx);
        sa[tid] = e;
        tmp[tid] = e;
    }
    __syncthreads();
    for (int s = Sz / 2; s > 0; s >>= 1) {
        if (tid < s) tmp[tid] += tmp[tid + s];
        __syncthreads();
    }
    const float inv = 1.f / tmp[0];
    __syncthreads();
    if (tid < Sz) {
        float al = sa[tid] * inv;
        sa[tid] = al;
        alpha_out[b * Sz + tid] = al;
    }
    __syncthreads();

    for (int d = tid; d < 2 * Hz; d += 256) {
        float s = 0.f;
#pragma unroll 8
        for (int t = 0; t < Sz; t++)
            s += sa[t] * enc[(t * Bz + b) * 2 * Hz + d];
        g_context[b * 2 * Hz + d] = s;
    }
}

// ---------------------------------------------------------------------------
// LSTM cell elementwise: gate order i, f, g, o
// ---------------------------------------------------------------------------
__global__ __launch_bounds__(256) void lstm_cell_kernel(
    const float* __restrict__ c_old, float* __restrict__ h_out,
    float* __restrict__ c_out) {
    const int idx = blockIdx.x * 256 + threadIdx.x;
    const int b = idx >> 10, j = idx & (Hz - 1);
    const float* g = g_gates + b * 4 * Hz;
    float gi = g[j], gf = g[Hz + j], gg = g[2 * Hz + j], go = g[3 * Hz + j];
    float si = 1.f / (1.f + expf(-gi));
    float sf = 1.f / (1.f + expf(-gf));
    float so = 1.f / (1.f + expf(-go));
    float cn = sf * c_old[idx] + si * tanhf(gg);
    float hn = so * tanhf(cn);
    c_out[idx] = cn;
    h_out[idx] = hn;
}

// ---------------------------------------------------------------------------
extern "C" void kernel_launch(void* const* d_in, const int* in_sizes, int n_in,
                              void* d_out, int out_size) {
    const int*   token  = (const int*)d_in[0];
    const float* hidden = (const float*)d_in[1];
    const float* cell   = (const float*)d_in[2];
    const float* enc    = (const float*)d_in[3];
    const float* emb    = (const float*)d_in[4];
    const float* Wenc   = (const float*)d_in[5];
    const float* Wdec   = (const float*)d_in[6];
    const float* vw     = (const float*)d_in[7];
    const float* Wih0   = (const float*)d_in[8];
    const float* Whh0   = (const float*)d_in[9];
    const float* bih0   = (const float*)d_in[10];
    const float* bhh0   = (const float*)d_in[11];
    const float* Wih1   = (const float*)d_in[12];
    const float* Whh1   = (const float*)d_in[13];
    const float* bih1   = (const float*)d_in[14];
    const float* bhh1   = (const float*)d_in[15];
    const float* fcW    = (const float*)d_in[16];
    const float* fcb    = (const float*)d_in[17];

    float* out    = (float*)d_out;
    float* logits = out + OFF_LOGITS;
    float* h0o    = out + OFF_H0;
    float* h1o    = out + OFF_H1;
    float* c0o    = out + OFF_C0;
    float* c1o    = out + OFF_C1;
    float* alpha  = out + OFF_ALPHA;

    // 1) dproj = hidden[1] @ W_dec^T   (64 x 512, K=1024)
    {
        DprojCfg cfg{Hz, hidden, Wdec};
        mma_gemm<<<dim3(Az / 64, 1), 256>>>(cfg);
    }
    // 2) attention energy + score partials (rows 8192, cols 512, K=2048)
    {
        AttnCfg cfg{2 * Hz, enc, Wenc, vw};
        attn_mma_kernel<<<dim3(Az / 64, (Sz * Bz) / 64), 256>>>(cfg);
    }
    // 3) softmax + context
    softmax_context_kernel<<<Bz, 256>>>(enc, alpha);
    // 4) LSTM layer 0 gates (64 x 4096, K=3584)
    {
        Lstm0Cfg cfg{Ez + 2 * Hz + Hz, token, emb, hidden, Wih0, Whh0, bih0, bhh0};
        mma_gemm<<<dim3(4 * Hz / 64, 1), 256>>>(cfg);
    }
    lstm_cell_kernel<<<(Bz * Hz) / 256, 256>>>(cell, h0o, c0o);
    // 5) LSTM layer 1 gates (64 x 4096, K=2048)
    {
        Lstm1Cfg cfg{2 * Hz, h0o, hidden, Wih1, Whh1, bih1, bhh1};
        mma_gemm<<<dim3(4 * Hz / 64, 1), 256>>>(cfg);
    }
    lstm_cell_kernel<<<(Bz * Hz) / 256, 256>>>(cell + Bz * Hz, h1o, c1o);
    // 6) fc logits (64 x 32000, K=3072)
    {
        FcCfg cfg{3 * Hz, h1o, fcW, fcb, logits};
        mma_gemm<<<dim3(Vz / 64, 1), 256>>>(cfg);
    }
    (void)in_sizes; (void)n_in; (void)out_size;
}

// round 5
// speedup vs baseline: 3.0156x; 1.3164x over previous
#include <cuda_runtime.h>
#include <cuda_bf16.h>
#include <stdint.h>
#include <math.h>

// Problem dims
#define Bz 64
#define Sz 128
#define Hz 1024
#define Ez 512
#define Az 512
#define Vz 32000

// Output layout (floats): logits[B*V], new_hidden[2*B*H], new_cell[2*B*H], alpha[B*S]
#define OFF_LOGITS 0
#define OFF_H0     (Bz*Vz)
#define OFF_H1     (OFF_H0 + Bz*Hz)
#define OFF_C0     (OFF_H0 + 2*Bz*Hz)
#define OFF_C1     (OFF_C0 + Bz*Hz)
#define OFF_ALPHA  (OFF_C0 + 2*Bz*Hz)

#define KC 4   // split-K factor for small-grid GEMMs

// Scratch (device globals; no allocations allowed)
__device__ float g_dproj[Bz * Az];            // reduced dproj (64 x 512)
__device__ float g_dpp[KC][Bz * Az];          // dproj split-K partials
__device__ float g_scorep[8 * Bz * Sz];       // 8 column-block partial scores
__device__ float g_context[Bz * 2 * Hz];      // attention context (64 x 2048)
__device__ float g_gp[KC][Bz * 4 * Hz];       // LSTM gate split-K partials

#define LDSTRIDE 40          // b16 elems per smem row (32 data + 8 pad)
#define SSTRIDE  (64 * LDSTRIDE)   // elems per smem stage

// ---------------------------------------------------------------------------
// MMA helpers
// ---------------------------------------------------------------------------
__device__ __forceinline__ uint32_t smem_u32(const void* p) {
    return (uint32_t)__cvta_generic_to_shared(p);
}

__device__ __forceinline__ void ldm_x4(uint32_t addr, uint32_t& r0, uint32_t& r1,
                                       uint32_t& r2, uint32_t& r3) {
    asm volatile("ldmatrix.sync.aligned.m8n8.x4.shared.b16 {%0,%1,%2,%3}, [%4];"
                 : "=r"(r0), "=r"(r1), "=r"(r2), "=r"(r3) : "r"(addr));
}

__device__ __forceinline__ void mma_bf16(float* c, const uint32_t a[4],
                                         uint32_t b0, uint32_t b1) {
    asm volatile(
        "mma.sync.aligned.m16n8k16.row.col.f32.bf16.bf16.f32 "
        "{%0,%1,%2,%3}, {%4,%5,%6,%7}, {%8,%9}, {%0,%1,%2,%3};"
        : "+f"(c[0]), "+f"(c[1]), "+f"(c[2]), "+f"(c[3])
        : "r"(a[0]), "r"(a[1]), "r"(a[2]), "r"(a[3]), "r"(b0), "r"(b1));
}

// Split one float4 into bf16 hi/lo and store 4 elements to each smem array.
__device__ __forceinline__ void split4(__nv_bfloat16* hi, __nv_bfloat16* lo,
                                       int idx, float4 v) {
    __nv_bfloat16 h0 = __float2bfloat16(v.x);
    __nv_bfloat16 h1 = __float2bfloat16(v.y);
    __nv_bfloat16 h2 = __float2bfloat16(v.z);
    __nv_bfloat16 h3 = __float2bfloat16(v.w);
    __nv_bfloat16 l0 = __float2bfloat16(v.x - __bfloat162float(h0));
    __nv_bfloat16 l1 = __float2bfloat16(v.y - __bfloat162float(h1));
    __nv_bfloat16 l2 = __float2bfloat16(v.z - __bfloat162float(h2));
    __nv_bfloat16 l3 = __float2bfloat16(v.w - __bfloat162float(h3));
    __nv_bfloat162* H = (__nv_bfloat162*)(hi + idx);
    __nv_bfloat162* L = (__nv_bfloat162*)(lo + idx);
    __nv_bfloat162 t;
    t.x = h0; t.y = h1; H[0] = t;
    t.x = h2; t.y = h3; H[1] = t;
    t.x = l0; t.y = l1; L[0] = t;
    t.x = l2; t.y = l3; L[1] = t;
}

__device__ __forceinline__ float4 ld4(const float* p) {
    return *(const float4*)p;
}

// ---------------------------------------------------------------------------
// Double-buffered mainloop over K range [kb, ke):
// C[64,64] tile of A[M,K] @ B[N,K]^T via bf16 hi/lo 3-pass mma.
// Order per iter: prefetch regs -> mma(stage st) -> split/store(stage st^1) -> sync
// ---------------------------------------------------------------------------
template <class Cfg>
__device__ __forceinline__ void run_mainloop(const Cfg& cfg, int bm, int bn,
                                             int kb, int ke,
                                             __nv_bfloat16* Ah, __nv_bfloat16* Al,
                                             __nv_bfloat16* Bh, __nv_bfloat16* Bl,
                                             float acc[4][4]) {
    const int tid  = threadIdx.x;
    const int row  = tid >> 2;            // 0..63
    const int c4   = (tid & 3) << 2;      // 0,4,8,12
    const int lane = tid & 31;
    const int wid  = tid >> 5;
    const int wm   = (wid & 3) << 4;      // warp M offset
    const int wn   = (wid >> 2) << 5;     // warp N offset

    const int g = lane >> 3, r = lane & 7;
    const int a_off  = (wm + r + ((g & 1) << 3)) * LDSTRIDE + ((g >> 1) << 3);
    const int b_row  = r + ((g >> 1) << 3);
    const int b_col  = (g & 1) << 3;
    const int b_off0 = (wn + b_row) * LDSTRIDE + b_col;
    const int b_off1 = (wn + 16 + b_row) * LDSTRIDE + b_col;

    const uint32_t sAh = smem_u32(Ah), sAl = smem_u32(Al);
    const uint32_t sBh = smem_u32(Bh), sBl = smem_u32(Bl);

    float4 ra0, ra1, rb0, rb1;
    {
        const float* pa = cfg.rowA(bm + row, kb);
        const float* pb = cfg.rowB(bn + row, kb);
        ra0 = ld4(pa + c4);  ra1 = ld4(pa + c4 + 16);
        rb0 = ld4(pb + c4);  rb1 = ld4(pb + c4 + 16);
    }

    const int sidx = row * LDSTRIDE + c4;
    // prologue: fill stage 0
    split4(Ah, Al, sidx,      ra0);
    split4(Ah, Al, sidx + 16, ra1);
    split4(Bh, Bl, sidx,      rb0);
    split4(Bh, Bl, sidx + 16, rb1);
    __syncthreads();

    const int nIter = (ke - kb) >> 5;
    int st = 0;
    for (int it = 0; it < nIter; it++) {
        const bool more = (it + 1 < nIter);
        if (more) {  // issue next tile's global loads first
            const int kn = kb + ((it + 1) << 5);
            const float* pa = cfg.rowA(bm + row, kn);
            const float* pb = cfg.rowB(bn + row, kn);
            ra0 = ld4(pa + c4);  ra1 = ld4(pa + c4 + 16);
            rb0 = ld4(pb + c4);  rb1 = ld4(pb + c4 + 16);
        }
        const uint32_t sb = (uint32_t)st * (2 * SSTRIDE);  // stage byte offset
#pragma unroll
        for (int ks = 0; ks < 2; ks++) {
            const int ko = ks << 4;
            uint32_t ah[4], al_[4];
            ldm_x4(sAh + sb + 2 * (a_off + ko), ah[0], ah[1], ah[2], ah[3]);
            ldm_x4(sAl + sb + 2 * (a_off + ko), al_[0], al_[1], al_[2], al_[3]);
#pragma unroll
            for (int p = 0; p < 2; p++) {
                const int bo = (p ? b_off1 : b_off0) + ko;
                uint32_t bh[4], bl_[4];
                ldm_x4(sBh + sb + 2 * bo, bh[0], bh[1], bh[2], bh[3]);
                ldm_x4(sBl + sb + 2 * bo, bl_[0], bl_[1], bl_[2], bl_[3]);
                float* c0 = acc[2 * p];
                float* c1 = acc[2 * p + 1];
                mma_bf16(c0, ah,  bh[0], bh[1]);
                mma_bf16(c0, ah,  bl_[0], bl_[1]);
                mma_bf16(c0, al_, bh[0], bh[1]);
                mma_bf16(c1, ah,  bh[2], bh[3]);
                mma_bf16(c1, ah,  bl_[2], bl_[3]);
                mma_bf16(c1, al_, bh[2], bh[3]);
            }
        }
        if (more) {  // store next tile into the other stage
            const int so = (st ^ 1) * SSTRIDE + sidx;
            split4(Ah, Al, so,      ra0);
            split4(Ah, Al, so + 16, ra1);
            split4(Bh, Bl, so,      rb0);
            split4(Bh, Bl, so + 16, rb1);
        }
        __syncthreads();
        st ^= 1;
    }
}

// ---------------------------------------------------------------------------
// Generic GEMM kernel; grid.z = split-K chunk
// ---------------------------------------------------------------------------
template <class Cfg>
__global__ __launch_bounds__(256) void mma_gemm(Cfg cfg, int kchunk) {
    __shared__ __nv_bfloat16 Ah[2 * SSTRIDE], Al[2 * SSTRIDE];
    __shared__ __nv_bfloat16 Bh[2 * SSTRIDE], Bl[2 * SSTRIDE];
    float acc[4][4] = {};
    const int bm = blockIdx.y << 6, bn = blockIdx.x << 6;
    const int kc = blockIdx.z;
    run_mainloop(cfg, bm, bn, kc * kchunk, (kc + 1) * kchunk, Ah, Al, Bh, Bl, acc);

    const int lane = threadIdx.x & 31, wid = threadIdx.x >> 5;
    const int m0 = bm + ((wid & 3) << 4) + (lane >> 2);
    const int nb = bn + ((wid >> 2) << 5) + ((lane & 3) << 1);
#pragma unroll
    for (int j = 0; j < 4; j++) {
        const int n = nb + j * 8;
        cfg.store2(kc, m0,     n, acc[j][0], acc[j][1]);
        cfg.store2(kc, m0 + 8, n, acc[j][2], acc[j][3]);
    }
}

// ---- Configs ---------------------------------------------------------------
struct DprojCfg {
    int K;
    const float* hid;    // (L,B,H)
    const float* Wdec;   // (A,H)
    __device__ __forceinline__ const float* rowA(int m, int k0) const {
        return hid + (Bz + m) * Hz + k0;   // hidden[-1]
    }
    __device__ __forceinline__ const float* rowB(int n, int k0) const {
        return Wdec + n * Hz + k0;
    }
    __device__ __forceinline__ void store2(int kc, int m, int n, float v0, float v1) const {
        float2 t; t.x = v0; t.y = v1;
        *(float2*)&g_dpp[kc][m * Az + n] = t;
    }
};

struct Lstm0Cfg {
    int K;  // 3584
    const int* token;
    const float* emb;    // (V,E)
    const float* hid;    // layer 0 hidden
    const float* Wih;    // (4H, E+2H)
    const float* Whh;    // (4H, H)
    __device__ __forceinline__ const float* rowA(int m, int k0) const {
        if (k0 < Ez)          return emb + token[m] * Ez + k0;
        if (k0 < Ez + 2 * Hz) return g_context + m * 2 * Hz + (k0 - Ez);
        return hid + m * Hz + (k0 - Ez - 2 * Hz);
    }
    __device__ __forceinline__ const float* rowB(int n, int k0) const {
        if (k0 < Ez + 2 * Hz) return Wih + n * (Ez + 2 * Hz) + k0;
        return Whh + n * Hz + (k0 - Ez - 2 * Hz);
    }
    __device__ __forceinline__ void store2(int kc, int m, int n, float v0, float v1) const {
        float2 t; t.x = v0; t.y = v1;
        *(float2*)&g_gp[kc][m * 4 * Hz + n] = t;
    }
};

struct Lstm1Cfg {
    int K;  // 2048
    const float* h0new;
    const float* hid;    // layer 1 hidden
    const float* Wih;    // (4H, H)
    const float* Whh;    // (4H, H)
    __device__ __forceinline__ const float* rowA(int m, int k0) const {
        if (k0 < Hz) return h0new + m * Hz + k0;
        return hid + (Bz + m) * Hz + (k0 - Hz);
    }
    __device__ __forceinline__ const float* rowB(int n, int k0) const {
        if (k0 < Hz) return Wih + n * Hz + k0;
        return Whh + n * Hz + (k0 - Hz);
    }
    __device__ __forceinline__ void store2(int kc, int m, int n, float v0, float v1) const {
        float2 t; t.x = v0; t.y = v1;
        *(float2*)&g_gp[kc][m * 4 * Hz + n] = t;
    }
};

struct FcCfg {
    int K;  // 3072
    const float* h1new;
    const float* fcW;    // (V, 3H)
    const float* fcb;
    float* logits;
    __device__ __forceinline__ const float* rowA(int m, int k0) const {
        if (k0 < Hz) return h1new + m * Hz + k0;
        return g_context + m * 2 * Hz + (k0 - Hz);
    }
    __device__ __forceinline__ const float* rowB(int n, int k0) const {
        return fcW + n * 3 * Hz + k0;
    }
    __device__ __forceinline__ void store2(int, int m, int n, float v0, float v1) const {
        float2 t;
        t.x = v0 + fcb[n];
        t.y = v1 + fcb[n + 1];
        *(float2*)&logits[m * Vz + n] = t;
    }
};

// ---------------------------------------------------------------------------
// dproj partial reduce: g_dproj = sum_kc g_dpp[kc]
// ---------------------------------------------------------------------------
__global__ __launch_bounds__(256) void dproj_reduce_kernel() {
    const int i = blockIdx.x * 256 + threadIdx.x;  // 0 .. Bz*Az-1
    float s = 0.f;
#pragma unroll
    for (int z = 0; z < KC; z++) s += g_dpp[z][i];
    g_dproj[i] = s;
}

// ---------------------------------------------------------------------------
// Attention: energy GEMM + tanh + v-dot + per-row reduce into column partials
// ---------------------------------------------------------------------------
struct AttnCfg {
    int K;  // 2048
    const float* enc;    // (S*B, 2H)
    const float* Wenc;   // (A, 2H)
    const float* vw;     // (A,)
    __device__ __forceinline__ const float* rowA(int m, int k0) const {
        return enc + m * 2 * Hz + k0;
    }
    __device__ __forceinline__ const float* rowB(int n, int k0) const {
        return Wenc + n * 2 * Hz + k0;
    }
    __device__ __forceinline__ void store2(int, int, int, float, float) const {}
};

__global__ __launch_bounds__(256) void attn_mma_kernel(AttnCfg cfg) {
    __shared__ __nv_bfloat16 Ah[2 * SSTRIDE], Al[2 * SSTRIDE];
    __shared__ __nv_bfloat16 Bh[2 * SSTRIDE], Bl[2 * SSTRIDE];
    __shared__ float red[64][2];
    float acc[4][4] = {};
    const int bm = blockIdx.y << 6, bn = blockIdx.x << 6;
    run_mainloop(cfg, bm, bn, 0, cfg.K, Ah, Al, Bh, Bl, acc);

    const int lane = threadIdx.x & 31, wid = threadIdx.x >> 5;
    const int wnI = wid >> 2;
    const int ml  = ((wid & 3) << 4) + (lane >> 2);
    const int b0  = (bm + ml) & (Bz - 1);
    const int b1  = (bm + ml + 8) & (Bz - 1);
    const int nb  = bn + (wnI << 5) + ((lane & 3) << 1);

    float rs0 = 0.f, rs1 = 0.f;
#pragma unroll
    for (int j = 0; j < 4; j++) {
        const int n = nb + j * 8;
        const float v0 = cfg.vw[n], v1 = cfg.vw[n + 1];
        rs0 += v0 * tanhf(acc[j][0] + g_dproj[b0 * Az + n]);
        rs0 += v1 * tanhf(acc[j][1] + g_dproj[b0 * Az + n + 1]);
        rs1 += v0 * tanhf(acc[j][2] + g_dproj[b1 * Az + n]);
        rs1 += v1 * tanhf(acc[j][3] + g_dproj[b1 * Az + n + 1]);
    }
    rs0 += __shfl_xor_sync(0xffffffffu, rs0, 1);
    rs0 += __shfl_xor_sync(0xffffffffu, rs0, 2);
    rs1 += __shfl_xor_sync(0xffffffffu, rs1, 1);
    rs1 += __shfl_xor_sync(0xffffffffu, rs1, 2);
    if ((lane & 3) == 0) {
        red[ml][wnI]     = rs0;
        red[ml + 8][wnI] = rs1;
    }
    __syncthreads();
    if (threadIdx.x < 64)
        g_scorep[blockIdx.x * (Bz * Sz) + bm + threadIdx.x] =
            red[threadIdx.x][0] + red[threadIdx.x][1];
}

// ---------------------------------------------------------------------------
// Softmax over S per batch row + context = alpha @ enc_t. One block per b.
// ---------------------------------------------------------------------------
__global__ __launch_bounds__(256) void softmax_context_kernel(
    const float* __restrict__ enc, float* __restrict__ alpha_out) {
    const int b = blockIdx.x;
    const int tid = threadIdx.x;
    __shared__ float sa[Sz];
    __shared__ float tmp[Sz];

    if (tid < Sz) {
        float sc = 0.f;
#pragma unroll
        for (int p = 0; p < 8; p++) sc += g_scorep[p * (Bz * Sz) + tid * Bz + b];
        sa[tid] = sc;
        tmp[tid] = sc;
    }
    __syncthreads();
    for (int s = Sz / 2; s > 0; s >>= 1) {
        if (tid < s) tmp[tid] = fmaxf(tmp[tid], tmp[tid + s]);
        __syncthreads();
    }
    const float mx = tmp[0];
    __syncthreads();
    if (tid < Sz) {
        float e = expf(sa[tid] - mx);
        sa[tid] = e;
        tmp[tid] = e;
    }
    __syncthreads();
    for (int s = Sz / 2; s > 0; s >>= 1) {
        if (tid < s) tmp[tid] += tmp[tid + s];
        __syncthreads();
    }
    const float inv = 1.f / tmp[0];
    __syncthreads();
    if (tid < Sz) {
        float al = sa[tid] * inv;
        sa[tid] = al;
        alpha_out[b * Sz + tid] = al;
    }
    __syncthreads();

    for (int d = tid; d < 2 * Hz; d += 256) {
        float s = 0.f;
#pragma unroll 8
        for (int t = 0; t < Sz; t++)
            s += sa[t] * enc[(t * Bz + b) * 2 * Hz + d];
        g_context[b * 2 * Hz + d] = s;
    }
}

// ---------------------------------------------------------------------------
// LSTM cell elementwise: sums split-K gate partials + biases. Gate order i,f,g,o.
// ---------------------------------------------------------------------------
__global__ __launch_bounds__(256) void lstm_cell_kernel(
    const float* __restrict__ c_old,
    const float* __restrict__ bih, const float* __restrict__ bhh,
    float* __restrict__ h_out, float* __restrict__ c_out) {
    const int idx = blockIdx.x * 256 + threadIdx.x;
    const int b = idx >> 10, j = idx & (Hz - 1);
    const int base = b * 4 * Hz;
    float gi = bih[j]          + bhh[j];
    float gf = bih[Hz + j]     + bhh[Hz + j];
    float gg = bih[2 * Hz + j] + bhh[2 * Hz + j];
    float go = bih[3 * Hz + j] + bhh[3 * Hz + j];
#pragma unroll
    for (int z = 0; z < KC; z++) {
        gi += g_gp[z][base + j];
        gf += g_gp[z][base + Hz + j];
        gg += g_gp[z][base + 2 * Hz + j];
        go += g_gp[z][base + 3 * Hz + j];
    }
    float si = 1.f / (1.f + expf(-gi));
    float sf = 1.f / (1.f + expf(-gf));
    float so = 1.f / (1.f + expf(-go));
    float cn = sf * c_old[idx] + si * tanhf(gg);
    float hn = so * tanhf(cn);
    c_out[idx] = cn;
    h_out[idx] = hn;
}

// ---------------------------------------------------------------------------
extern "C" void kernel_launch(void* const* d_in, const int* in_sizes, int n_in,
                              void* d_out, int out_size) {
    const int*   token  = (const int*)d_in[0];
    const float* hidden = (const float*)d_in[1];
    const float* cell   = (const float*)d_in[2];
    const float* enc    = (const float*)d_in[3];
    const float* emb    = (const float*)d_in[4];
    const float* Wenc   = (const float*)d_in[5];
    const float* Wdec   = (const float*)d_in[6];
    const float* vw     = (const float*)d_in[7];
    const float* Wih0   = (const float*)d_in[8];
    const float* Whh0   = (const float*)d_in[9];
    const float* bih0   = (const float*)d_in[10];
    const float* bhh0   = (const float*)d_in[11];
    const float* Wih1   = (const float*)d_in[12];
    const float* Whh1   = (const float*)d_in[13];
    const float* bih1   = (const float*)d_in[14];
    const float* bhh1   = (const float*)d_in[15];
    const float* fcW    = (const float*)d_in[16];
    const float* fcb    = (const float*)d_in[17];

    float* out    = (float*)d_out;
    float* logits = out + OFF_LOGITS;
    float* h0o    = out + OFF_H0;
    float* h1o    = out + OFF_H1;
    float* c0o    = out + OFF_C0;
    float* c1o    = out + OFF_C1;
    float* alpha  = out + OFF_ALPHA;

    // 1) dproj = hidden[1] @ W_dec^T   (64 x 512, K=1024, split-K=4)
    {
        DprojCfg cfg{Hz, hidden, Wdec};
        mma_gemm<<<dim3(Az / 64, 1, KC), 256>>>(cfg, Hz / KC);
    }
    dproj_reduce_kernel<<<(Bz * Az) / 256, 256>>>();
    // 2) attention energy + score partials (rows 8192, cols 512, K=2048)
    {
        AttnCfg cfg{2 * Hz, enc, Wenc, vw};
        attn_mma_kernel<<<dim3(Az / 64, (Sz * Bz) / 64), 256>>>(cfg);
    }
    // 3) softmax + context
    softmax_context_kernel<<<Bz, 256>>>(enc, alpha);
    // 4) LSTM layer 0 gates (64 x 4096, K=3584, split-K=4)
    {
        Lstm0Cfg cfg{Ez + 2 * Hz + Hz, token, emb, hidden, Wih0, Whh0};
        mma_gemm<<<dim3(4 * Hz / 64, 1, KC), 256>>>(cfg, (Ez + 3 * Hz) / KC);
    }
    lstm_cell_kernel<<<(Bz * Hz) / 256, 256>>>(cell, bih0, bhh0, h0o, c0o);
    // 5) LSTM layer 1 gates (64 x 4096, K=2048, split-K=4)
    {
        Lstm1Cfg cfg{2 * Hz, h0o, hidden, Wih1, Whh1};
        mma_gemm<<<dim3(4 * Hz / 64, 1, KC), 256>>>(cfg, 2 * Hz / KC);
    }
    lstm_cell_kernel<<<(Bz * Hz) / 256, 256>>>(cell + Bz * Hz, bih1, bhh1, h1o, c1o);
    // 6) fc logits (64 x 32000, K=3072)
    {
        FcCfg cfg{3 * Hz, h1o, fcW, fcb, logits};
        mma_gemm<<<dim3(Vz / 64, 1, 1), 256>>>(cfg, 3 * Hz);
    }
    (void)in_sizes; (void)n_in; (void)out_size;
}

// round 16
// speedup vs baseline: 3.2454x; 1.0762x over previous
#include <cuda_runtime.h>
#include <cuda_bf16.h>
#include <stdint.h>
#include <math.h>

// Problem dims
#define Bz 64
#define Sz 128
#define Hz 1024
#define Ez 512
#define Az 512
#define Vz 32000

// Output layout (floats): logits[B*V], new_hidden[2*B*H], new_cell[2*B*H], alpha[B*S]
#define OFF_LOGITS 0
#define OFF_H0     (Bz*Vz)
#define OFF_H1     (OFF_H0 + Bz*Hz)
#define OFF_C0     (OFF_H0 + 2*Bz*Hz)
#define OFF_C1     (OFF_C0 + Bz*Hz)
#define OFF_ALPHA  (OFF_C0 + 2*Bz*Hz)

#define KC 8   // split-K factor for small-grid GEMMs

// Scratch (device globals; no allocations allowed)
__device__ float g_dproj[Bz * Az];            // reduced dproj (64 x 512)
__device__ float g_dpp[KC][Bz * Az];          // dproj split-K partials
__device__ float g_scorep[8 * Bz * Sz];       // 8 column-block partial scores
__device__ float g_alpha[Bz * Sz];            // softmax weights
__device__ float g_context[Bz * 2 * Hz];      // attention context (64 x 2048)
__device__ float g_gp[KC][Bz * 4 * Hz];       // LSTM gate split-K partials

#define LDSTRIDE 40          // b16 elems per smem row (32 data + 8 pad)
#define SSTRIDE  (64 * LDSTRIDE)   // elems per smem stage

// ---------------------------------------------------------------------------
// MMA helpers
// ---------------------------------------------------------------------------
__device__ __forceinline__ uint32_t smem_u32(const void* p) {
    return (uint32_t)__cvta_generic_to_shared(p);
}

__device__ __forceinline__ void ldm_x4(uint32_t addr, uint32_t& r0, uint32_t& r1,
                                       uint32_t& r2, uint32_t& r3) {
    asm volatile("ldmatrix.sync.aligned.m8n8.x4.shared.b16 {%0,%1,%2,%3}, [%4];"
                 : "=r"(r0), "=r"(r1), "=r"(r2), "=r"(r3) : "r"(addr));
}

__device__ __forceinline__ void mma_bf16(float* c, const uint32_t a[4],
                                         uint32_t b0, uint32_t b1) {
    asm volatile(
        "mma.sync.aligned.m16n8k16.row.col.f32.bf16.bf16.f32 "
        "{%0,%1,%2,%3}, {%4,%5,%6,%7}, {%8,%9}, {%0,%1,%2,%3};"
        : "+f"(c[0]), "+f"(c[1]), "+f"(c[2]), "+f"(c[3])
        : "r"(a[0]), "r"(a[1]), "r"(a[2]), "r"(a[3]), "r"(b0), "r"(b1));
}

// Split one float4 into bf16 hi/lo and store 4 elements to each smem array.
__device__ __forceinline__ void split4(__nv_bfloat16* hi, __nv_bfloat16* lo,
                                       int idx, float4 v) {
    __nv_bfloat16 h0 = __float2bfloat16(v.x);
    __nv_bfloat16 h1 = __float2bfloat16(v.y);
    __nv_bfloat16 h2 = __float2bfloat16(v.z);
    __nv_bfloat16 h3 = __float2bfloat16(v.w);
    __nv_bfloat16 l0 = __float2bfloat16(v.x - __bfloat162float(h0));
    __nv_bfloat16 l1 = __float2bfloat16(v.y - __bfloat162float(h1));
    __nv_bfloat16 l2 = __float2bfloat16(v.z - __bfloat162float(h2));
    __nv_bfloat16 l3 = __float2bfloat16(v.w - __bfloat162float(h3));
    __nv_bfloat162* H = (__nv_bfloat162*)(hi + idx);
    __nv_bfloat162* L = (__nv_bfloat162*)(lo + idx);
    __nv_bfloat162 t;
    t.x = h0; t.y = h1; H[0] = t;
    t.x = h2; t.y = h3; H[1] = t;
    t.x = l0; t.y = l1; L[0] = t;
    t.x = l2; t.y = l3; L[1] = t;
}

__device__ __forceinline__ float4 ld4(const float* p) {
    return *(const float4*)p;
}

// ---------------------------------------------------------------------------
// Double-buffered mainloop over K range [kb, ke):
// C[64,64] tile of A[M,K] @ B[N,K]^T via bf16 hi/lo 3-pass mma.
// ---------------------------------------------------------------------------
template <class Cfg>
__device__ __forceinline__ void run_mainloop(const Cfg& cfg, int bm, int bn,
                                             int kb, int ke,
                                             __nv_bfloat16* Ah, __nv_bfloat16* Al,
                                             __nv_bfloat16* Bh, __nv_bfloat16* Bl,
                                             float acc[4][4]) {
    const int tid  = threadIdx.x;
    const int row  = tid >> 2;            // 0..63
    const int c4   = (tid & 3) << 2;      // 0,4,8,12
    const int lane = tid & 31;
    const int wid  = tid >> 5;
    const int wm   = (wid & 3) << 4;      // warp M offset
    const int wn   = (wid >> 2) << 5;     // warp N offset

    const int g = lane >> 3, r = lane & 7;
    const int a_off  = (wm + r + ((g & 1) << 3)) * LDSTRIDE + ((g >> 1) << 3);
    const int b_row  = r + ((g >> 1) << 3);
    const int b_col  = (g & 1) << 3;
    const int b_off0 = (wn + b_row) * LDSTRIDE + b_col;
    const int b_off1 = (wn + 16 + b_row) * LDSTRIDE + b_col;

    const uint32_t sAh = smem_u32(Ah), sAl = smem_u32(Al);
    const uint32_t sBh = smem_u32(Bh), sBl = smem_u32(Bl);

    float4 ra0, ra1, rb0, rb1;
    {
        const float* pa = cfg.rowA(bm + row, kb);
        const float* pb = cfg.rowB(bn + row, kb);
        ra0 = ld4(pa + c4);  ra1 = ld4(pa + c4 + 16);
        rb0 = ld4(pb + c4);  rb1 = ld4(pb + c4 + 16);
    }

    const int sidx = row * LDSTRIDE + c4;
    split4(Ah, Al, sidx,      ra0);
    split4(Ah, Al, sidx + 16, ra1);
    split4(Bh, Bl, sidx,      rb0);
    split4(Bh, Bl, sidx + 16, rb1);
    __syncthreads();

    const int nIter = (ke - kb) >> 5;
    int st = 0;
    for (int it = 0; it < nIter; it++) {
        const bool more = (it + 1 < nIter);
        if (more) {
            const int kn = kb + ((it + 1) << 5);
            const float* pa = cfg.rowA(bm + row, kn);
            const float* pb = cfg.rowB(bn + row, kn);
            ra0 = ld4(pa + c4);  ra1 = ld4(pa + c4 + 16);
            rb0 = ld4(pb + c4);  rb1 = ld4(pb + c4 + 16);
        }
        const uint32_t sb = (uint32_t)st * (2 * SSTRIDE);
#pragma unroll
        for (int ks = 0; ks < 2; ks++) {
            const int ko = ks << 4;
            uint32_t ah[4], al_[4];
            ldm_x4(sAh + sb + 2 * (a_off + ko), ah[0], ah[1], ah[2], ah[3]);
            ldm_x4(sAl + sb + 2 * (a_off + ko), al_[0], al_[1], al_[2], al_[3]);
#pragma unroll
            for (int p = 0; p < 2; p++) {
                const int bo = (p ? b_off1 : b_off0) + ko;
                uint32_t bh[4], bl_[4];
                ldm_x4(sBh + sb + 2 * bo, bh[0], bh[1], bh[2], bh[3]);
                ldm_x4(sBl + sb + 2 * bo, bl_[0], bl_[1], bl_[2], bl_[3]);
                float* c0 = acc[2 * p];
                float* c1 = acc[2 * p + 1];
                mma_bf16(c0, ah,  bh[0], bh[1]);
                mma_bf16(c0, ah,  bl_[0], bl_[1]);
                mma_bf16(c0, al_, bh[0], bh[1]);
                mma_bf16(c1, ah,  bh[2], bh[3]);
                mma_bf16(c1, ah,  bl_[2], bl_[3]);
                mma_bf16(c1, al_, bh[2], bh[3]);
            }
        }
        if (more) {
            const int so = (st ^ 1) * SSTRIDE + sidx;
            split4(Ah, Al, so,      ra0);
            split4(Ah, Al, so + 16, ra1);
            split4(Bh, Bl, so,      rb0);
            split4(Bh, Bl, so + 16, rb1);
        }
        __syncthreads();
        st ^= 1;
    }
}

// ---------------------------------------------------------------------------
// Generic GEMM kernel; grid.z = split-K chunk
// ---------------------------------------------------------------------------
template <class Cfg>
__global__ __launch_bounds__(256) void mma_gemm(Cfg cfg, int kchunk) {
    __shared__ __nv_bfloat16 Ah[2 * SSTRIDE], Al[2 * SSTRIDE];
    __shared__ __nv_bfloat16 Bh[2 * SSTRIDE], Bl[2 * SSTRIDE];
    float acc[4][4] = {};
    const int bm = blockIdx.y << 6, bn = blockIdx.x << 6;
    const int kc = blockIdx.z;
    run_mainloop(cfg, bm, bn, kc * kchunk, (kc + 1) * kchunk, Ah, Al, Bh, Bl, acc);

    const int lane = threadIdx.x & 31, wid = threadIdx.x >> 5;
    const int m0 = bm + ((wid & 3) << 4) + (lane >> 2);
    const int nb = bn + ((wid >> 2) << 5) + ((lane & 3) << 1);
#pragma unroll
    for (int j = 0; j < 4; j++) {
        const int n = nb + j * 8;
        cfg.store2(kc, m0,     n, acc[j][0], acc[j][1]);
        cfg.store2(kc, m0 + 8, n, acc[j][2], acc[j][3]);
    }
}

// ---- Configs ---------------------------------------------------------------
struct DprojCfg {
    int K;
    const float* hid;    // (L,B,H)
    const float* Wdec;   // (A,H)
    __device__ __forceinline__ const float* rowA(int m, int k0) const {
        return hid + (Bz + m) * Hz + k0;   // hidden[-1]
    }
    __device__ __forceinline__ const float* rowB(int n, int k0) const {
        return Wdec + n * Hz + k0;
    }
    __device__ __forceinline__ void store2(int kc, int m, int n, float v0, float v1) const {
        float2 t; t.x = v0; t.y = v1;
        *(float2*)&g_dpp[kc][m * Az + n] = t;
    }
};

struct Lstm0Cfg {
    int K;  // 3584
    const int* token;
    const float* emb;    // (V,E)
    const float* hid;    // layer 0 hidden
    const float* Wih;    // (4H, E+2H)
    const float* Whh;    // (4H, H)
    __device__ __forceinline__ const float* rowA(int m, int k0) const {
        if (k0 < Ez)          return emb + token[m] * Ez + k0;
        if (k0 < Ez + 2 * Hz) return g_context + m * 2 * Hz + (k0 - Ez);
        return hid + m * Hz + (k0 - Ez - 2 * Hz);
    }
    __device__ __forceinline__ const float* rowB(int n, int k0) const {
        if (k0 < Ez + 2 * Hz) return Wih + n * (Ez + 2 * Hz) + k0;
        return Whh + n * Hz + (k0 - Ez - 2 * Hz);
    }
    __device__ __forceinline__ void store2(int kc, int m, int n, float v0, float v1) const {
        float2 t; t.x = v0; t.y = v1;
        *(float2*)&g_gp[kc][m * 4 * Hz + n] = t;
    }
};

struct Lstm1Cfg {
    int K;  // 2048
    const float* h0new;
    const float* hid;    // layer 1 hidden
    const float* Wih;    // (4H, H)
    const float* Whh;    // (4H, H)
    __device__ __forceinline__ const float* rowA(int m, int k0) const {
        if (k0 < Hz) return h0new + m * Hz + k0;
        return hid + (Bz + m) * Hz + (k0 - Hz);
    }
    __device__ __forceinline__ const float* rowB(int n, int k0) const {
        if (k0 < Hz) return Wih + n * Hz + k0;
        return Whh + n * Hz + (k0 - Hz);
    }
    __device__ __forceinline__ void store2(int kc, int m, int n, float v0, float v1) const {
        float2 t; t.x = v0; t.y = v1;
        *(float2*)&g_gp[kc][m * 4 * Hz + n] = t;
    }
};

struct FcCfg {
    int K;  // 3072
    const float* h1new;
    const float* fcW;    // (V, 3H)
    const float* fcb;
    float* logits;
    __device__ __forceinline__ const float* rowA(int m, int k0) const {
        if (k0 < Hz) return h1new + m * Hz + k0;
        return g_context + m * 2 * Hz + (k0 - Hz);
    }
    __device__ __forceinline__ const float* rowB(int n, int k0) const {
        return fcW + n * 3 * Hz + k0;
    }
    __device__ __forceinline__ void store2(int, int m, int n, float v0, float v1) const {
        float2 t;
        t.x = v0 + fcb[n];
        t.y = v1 + fcb[n + 1];
        *(float2*)&logits[m * Vz + n] = t;
    }
};

// ---------------------------------------------------------------------------
// dproj partial reduce: g_dproj = sum_kc g_dpp[kc]
// ---------------------------------------------------------------------------
__global__ __launch_bounds__(256) void dproj_reduce_kernel() {
    const int i = blockIdx.x * 256 + threadIdx.x;
    float s = 0.f;
#pragma unroll
    for (int z = 0; z < KC; z++) s += g_dpp[z][i];
    g_dproj[i] = s;
}

// ---------------------------------------------------------------------------
// Attention: energy GEMM + tanh + v-dot + per-row reduce into column partials
// ---------------------------------------------------------------------------
struct AttnCfg {
    int K;  // 2048
    const float* enc;    // (S*B, 2H)
    const float* Wenc;   // (A, 2H)
    const float* vw;     // (A,)
    __device__ __forceinline__ const float* rowA(int m, int k0) const {
        return enc + m * 2 * Hz + k0;
    }
    __device__ __forceinline__ const float* rowB(int n, int k0) const {
        return Wenc + n * 2 * Hz + k0;
    }
    __device__ __forceinline__ void store2(int, int, int, float, float) const {}
};

__global__ __launch_bounds__(256) void attn_mma_kernel(AttnCfg cfg) {
    __shared__ __nv_bfloat16 Ah[2 * SSTRIDE], Al[2 * SSTRIDE];
    __shared__ __nv_bfloat16 Bh[2 * SSTRIDE], Bl[2 * SSTRIDE];
    __shared__ float red[64][2];
    float acc[4][4] = {};
    const int bm = blockIdx.y << 6, bn = blockIdx.x << 6;
    run_mainloop(cfg, bm, bn, 0, cfg.K, Ah, Al, Bh, Bl, acc);

    const int lane = threadIdx.x & 31, wid = threadIdx.x >> 5;
    const int wnI = wid >> 2;
    const int ml  = ((wid & 3) << 4) + (lane >> 2);
    const int b0  = (bm + ml) & (Bz - 1);
    const int b1  = (bm + ml + 8) & (Bz - 1);
    const int nb  = bn + (wnI << 5) + ((lane & 3) << 1);

    float rs0 = 0.f, rs1 = 0.f;
#pragma unroll
    for (int j = 0; j < 4; j++) {
        const int n = nb + j * 8;
        const float v0 = cfg.vw[n], v1 = cfg.vw[n + 1];
        rs0 += v0 * tanhf(acc[j][0] + g_dproj[b0 * Az + n]);
        rs0 += v1 * tanhf(acc[j][1] + g_dproj[b0 * Az + n + 1]);
        rs1 += v0 * tanhf(acc[j][2] + g_dproj[b1 * Az + n]);
        rs1 += v1 * tanhf(acc[j][3] + g_dproj[b1 * Az + n + 1]);
    }
    rs0 += __shfl_xor_sync(0xffffffffu, rs0, 1);
    rs0 += __shfl_xor_sync(0xffffffffu, rs0, 2);
    rs1 += __shfl_xor_sync(0xffffffffu, rs1, 1);
    rs1 += __shfl_xor_sync(0xffffffffu, rs1, 2);
    if ((lane & 3) == 0) {
        red[ml][wnI]     = rs0;
        red[ml + 8][wnI] = rs1;
    }
    __syncthreads();
    if (threadIdx.x < 64)
        g_scorep[blockIdx.x * (Bz * Sz) + bm + threadIdx.x] =
            red[threadIdx.x][0] + red[threadIdx.x][1];
}

// ---------------------------------------------------------------------------
// Softmax over S per batch row. One block per b (128 threads).
// Writes alpha to output AND g_alpha scratch.
// ---------------------------------------------------------------------------
__global__ __launch_bounds__(128) void softmax_kernel(float* __restrict__ alpha_out) {
    const int b = blockIdx.x;
    const int tid = threadIdx.x;  // 0..127 = s
    __shared__ float tmp[Sz];

    float sc = 0.f;
#pragma unroll
    for (int p = 0; p < 8; p++) sc += g_scorep[p * (Bz * Sz) + tid * Bz + b];
    tmp[tid] = sc;
    __syncthreads();
    for (int s = Sz / 2; s > 0; s >>= 1) {
        if (tid < s) tmp[tid] = fmaxf(tmp[tid], tmp[tid + s]);
        __syncthreads();
    }
    const float mx = tmp[0];
    __syncthreads();
    const float e = expf(sc - mx);
    tmp[tid] = e;
    __syncthreads();
    for (int s = Sz / 2; s > 0; s >>= 1) {
        if (tid < s) tmp[tid] += tmp[tid + s];
        __syncthreads();
    }
    const float al = e / tmp[0];
    alpha_out[b * Sz + tid] = al;
    g_alpha[b * Sz + tid] = al;
}

// ---------------------------------------------------------------------------
// Context: context[b, d] = sum_s alpha[b,s] * enc[(s*B + b)*2H + d]
// grid (2H/256, B); thread owns one d column. High MLP via 4-way unroll.
// ---------------------------------------------------------------------------
__global__ __launch_bounds__(256) void context_kernel(const float* __restrict__ enc) {
    const int b = blockIdx.y;
    const int d = blockIdx.x * 256 + threadIdx.x;
    __shared__ float sa[Sz];
    if (threadIdx.x < Sz) sa[threadIdx.x] = g_alpha[b * Sz + threadIdx.x];
    __syncthreads();

    const float* __restrict__ base = enc + b * 2 * Hz + d;
    float s0 = 0.f, s1 = 0.f, s2 = 0.f, s3 = 0.f;
#pragma unroll
    for (int t = 0; t < Sz; t += 4) {
        s0 += sa[t]     * base[(size_t)(t)     * (Bz * 2 * Hz)];
        s1 += sa[t + 1] * base[(size_t)(t + 1) * (Bz * 2 * Hz)];
        s2 += sa[t + 2] * base[(size_t)(t + 2) * (Bz * 2 * Hz)];
        s3 += sa[t + 3] * base[(size_t)(t + 3) * (Bz * 2 * Hz)];
    }
    g_context[b * 2 * Hz + d] = (s0 + s1) + (s2 + s3);
}

// ---------------------------------------------------------------------------
// LSTM cell elementwise: sums split-K gate partials + biases. Gate order i,f,g,o.
// ---------------------------------------------------------------------------
__global__ __launch_bounds__(256) void lstm_cell_kernel(
    const float* __restrict__ c_old,
    const float* __restrict__ bih, const float* __restrict__ bhh,
    float* __restrict__ h_out, float* __restrict__ c_out) {
    const int idx = blockIdx.x * 256 + threadIdx.x;
    const int b = idx >> 10, j = idx & (Hz - 1);
    const int base = b * 4 * Hz;
    float gi = bih[j]          + bhh[j];
    float gf = bih[Hz + j]     + bhh[Hz + j];
    float gg = bih[2 * Hz + j] + bhh[2 * Hz + j];
    float go = bih[3 * Hz + j] + bhh[3 * Hz + j];
#pragma unroll
    for (int z = 0; z < KC; z++) {
        gi += g_gp[z][base + j];
        gf += g_gp[z][base + Hz + j];
        gg += g_gp[z][base + 2 * Hz + j];
        go += g_gp[z][base + 3 * Hz + j];
    }
    float si = 1.f / (1.f + expf(-gi));
    float sf = 1.f / (1.f + expf(-gf));
    float so = 1.f / (1.f + expf(-go));
    float cn = sf * c_old[idx] + si * tanhf(gg);
    float hn = so * tanhf(cn);
    c_out[idx] = cn;
    h_out[idx] = hn;
}

// ---------------------------------------------------------------------------
extern "C" void kernel_launch(void* const* d_in, const int* in_sizes, int n_in,
                              void* d_out, int out_size) {
    const int*   token  = (const int*)d_in[0];
    const float* hidden = (const float*)d_in[1];
    const float* cell   = (const float*)d_in[2];
    const float* enc    = (const float*)d_in[3];
    const float* emb    = (const float*)d_in[4];
    const float* Wenc   = (const float*)d_in[5];
    const float* Wdec   = (const float*)d_in[6];
    const float* vw     = (const float*)d_in[7];
    const float* Wih0   = (const float*)d_in[8];
    const float* Whh0   = (const float*)d_in[9];
    const float* bih0   = (const float*)d_in[10];
    const float* bhh0   = (const float*)d_in[11];
    const float* Wih1   = (const float*)d_in[12];
    const float* Whh1   = (const float*)d_in[13];
    const float* bih1   = (const float*)d_in[14];
    const float* bhh1   = (const float*)d_in[15];
    const float* fcW    = (const float*)d_in[16];
    const float* fcb    = (const float*)d_in[17];

    float* out    = (float*)d_out;
    float* logits = out + OFF_LOGITS;
    float* h0o    = out + OFF_H0;
    float* h1o    = out + OFF_H1;
    float* c0o    = out + OFF_C0;
    float* c1o    = out + OFF_C1;
    float* alpha  = out + OFF_ALPHA;

    // 1) dproj = hidden[1] @ W_dec^T   (64 x 512, K=1024, split-K=8)
    {
        DprojCfg cfg{Hz, hidden, Wdec};
        mma_gemm<<<dim3(Az / 64, 1, KC), 256>>>(cfg, Hz / KC);
    }
    dproj_reduce_kernel<<<(Bz * Az) / 256, 256>>>();
    // 2) attention energy + score partials (rows 8192, cols 512, K=2048)
    {
        AttnCfg cfg{2 * Hz, enc, Wenc, vw};
        attn_mma_kernel<<<dim3(Az / 64, (Sz * Bz) / 64), 256>>>(cfg);
    }
    // 3) softmax, then wide context
    softmax_kernel<<<Bz, 128>>>(alpha);
    context_kernel<<<dim3(2 * Hz / 256, Bz), 256>>>(enc);
    // 4) LSTM layer 0 gates (64 x 4096, K=3584, split-K=8)
    {
        Lstm0Cfg cfg{Ez + 2 * Hz + Hz, token, emb, hidden, Wih0, Whh0};
        mma_gemm<<<dim3(4 * Hz / 64, 1, KC), 256>>>(cfg, (Ez + 3 * Hz) / KC);
    }
    lstm_cell_kernel<<<(Bz * Hz) / 256, 256>>>(cell, bih0, bhh0, h0o, c0o);
    // 5) LSTM layer 1 gates (64 x 4096, K=2048, split-K=8)
    {
        Lstm1Cfg cfg{2 * Hz, h0o, hidden, Wih1, Whh1};
        mma_gemm<<<dim3(4 * Hz / 64, 1, KC), 256>>>(cfg, 2 * Hz / KC);
    }
    lstm_cell_kernel<<<(Bz * Hz) / 256, 256>>>(cell + Bz * Hz, bih1, bhh1, h1o, c1o);
    // 6) fc logits (64 x 32000, K=3072)
    {
        FcCfg cfg{3 * Hz, h1o, fcW, fcb, logits};
        mma_gemm<<<dim3(Vz / 64, 1, 1), 256>>>(cfg, 3 * Hz);
    }
    (void)in_sizes; (void)n_in; (void)out_size;
}